// round 17
// baseline (speedup 1.0000x reference)
#include <cuda_runtime.h>
#include <cuda_bf16.h>
#include <math.h>

// ---------------------------------------------------------------------------
// HybridConv: out[n] = MLP(RBF(sigmoid(dot(data[n], conv_w) + conv_b)))
// out = f(t), t = 2*sigmoid(logit)-1 = tanh(logit/2), f analytic on [-1,1].
// SINGLE LAUNCH. Prologue (2 syncs, no single-warp serialization):
//   ph1: 256 threads eval f at 32 Chebyshev nodes (thread = (node, 2 hidden
//        units), 8-lane shfl reduce); DCT weights computed concurrently
//   ph2: 4-term DCT partials + in-warp 8-lane shfl reduce -> s_e[12]
//   ph3: EVERY thread converts s_e -> 12 monomial coeffs via constant
//        integer T_k matrix (parallel, no further sync)
// Main loop: software-pipelined, warp-blocked 128-patch chunks, pointer-
// increment addressing, 512B-contiguous LDG.128, coalesced STG.32, degree-11
// Horner in fma.rn.f32x2. 7 CTAs/SM for latency cover.
// ---------------------------------------------------------------------------

#define NCOEF 12   // monomial degree 11
#define BASIS 8
#define HIDDEN 16

// Chebyshev T_k power-basis coefficients (exact integers), T[k][j] = coeff of x^j
__device__ __constant__ float c_T[NCOEF][NCOEF] = {
    {   1,    0,    0,    0,     0,     0,    0,    0,     0,     0,    0,    0},
    {   0,    1,    0,    0,     0,     0,    0,    0,     0,     0,    0,    0},
    {  -1,    0,    2,    0,     0,     0,    0,    0,     0,     0,    0,    0},
    {   0,   -3,    0,    4,     0,     0,    0,    0,     0,     0,    0,    0},
    {   1,    0,   -8,    0,     8,     0,    0,    0,     0,     0,    0,    0},
    {   0,    5,    0,  -20,     0,    16,    0,    0,     0,     0,    0,    0},
    {  -1,    0,   18,    0,   -48,     0,   32,    0,     0,     0,    0,    0},
    {   0,   -7,    0,   56,     0,  -112,    0,   64,     0,     0,    0,    0},
    {   1,    0,  -32,    0,   160,     0, -256,    0,   128,     0,    0,    0},
    {   0,    9,    0, -120,     0,   432,    0, -576,     0,   256,    0,    0},
    {  -1,    0,   50,    0,  -400,     0, 1120,    0, -1280,     0,  512,    0},
    {   0,  -11,    0,  220,     0, -1232,    0, 2816,     0, -2816,    0, 1024}
};

#define FMA2(d, a, b, c) \
    asm("fma.rn.f32x2 %0, %1, %2, %3;" \
        : "=l"(d) : "l"(a), "l"(b), "l"(c))
#define PACK2(d, lo, hi) \
    asm("mov.b64 %0, {%1, %2};" : "=l"(d) : "f"(lo), "f"(hi))
#define UNPACK2(lo, hi, s) \
    asm("mov.b64 {%0, %1}, %2;" : "=f"(lo), "=f"(hi) : "l"(s))

__device__ __forceinline__ float fast_tanh(float x) {
    float y;
    asm("tanh.approx.f32 %0, %1;" : "=f"(y) : "f"(x));
    return y;
}

// ---- single fused kernel --------------------------------------------------
__global__ void __launch_bounds__(256, 7)
hybridconv_kernel(const float4* __restrict__ data,
                  const float* __restrict__ conv_w,
                  const float* __restrict__ conv_b,
                  const float* __restrict__ basis,
                  const float* __restrict__ w1v,
                  const float* __restrict__ b1v,
                  const float* __restrict__ w2v,
                  const float* __restrict__ b2v,
                  float* __restrict__ out, int nChunks, int n) {
    __shared__ float s_f[32];          // f at 32 Chebyshev nodes
    __shared__ float s_e[NCOEF];       // Chebyshev coefficients (scaled)

    const int tid    = threadIdx.x;
    const int lane   = tid & 31;
    const int gid    = blockIdx.x * blockDim.x + tid;
    const int warpId = gid >> 5;
    const int nWarps = (gridDim.x * blockDim.x) >> 5;

    // ---- pre-issue FIRST chunk's loads (overlap with prologue) ------------
    int chunk = warpId;
    bool valid = chunk < nChunks;
    const int step = nWarps << 7;
    const float4* p = data + (warpId << 7) + lane;
    float*        o = out  + (warpId << 7) + lane;
    float4 v0, v1, v2, v3;
    if (valid) {
        v0 = __ldcs(p);
        v1 = __ldcs(p + 32);
        v2 = __ldcs(p + 64);
        v3 = __ldcs(p + 96);
    }

    // ---- prologue phase 1: f at 32 nodes, ALL 256 threads -----------------
    {
        const int node = tid >> 3;
        const int g    = tid & 7;

        float t_node = cospif((float)(2 * node + 1) * (1.0f / 64.0f));
        float a = 0.5f + 0.5f * t_node;

        float feats[BASIS];
#pragma unroll
        for (int j = 0; j < BASIS; j++) {
            float s = 0.0f;
#pragma unroll
            for (int k = 0; k < 4; k++) {
                float d = a - basis[j * 4 + k];
                s = fmaf(d, d, s);
            }
            feats[j] = __expf(-s);           // GAMMA = 1
        }
        float v = 0.0f;
#pragma unroll
        for (int u = 0; u < 2; u++) {
            int h = g + u * 8;
            float pp = b1v[h];
#pragma unroll
            for (int j = 0; j < BASIS; j++)
                pp = fmaf(feats[j], w1v[j * HIDDEN + h], pp);
            v = fmaf(fast_tanh(pp), w2v[h], v);
        }
        // reduce over the 8 threads of this node (all lanes shuffle)
#pragma unroll
        for (int off = 4; off; off >>= 1)
            v += __shfl_xor_sync(0xFFFFFFFFu, v, off);
        if (g == 0) s_f[node] = v + b2v[0];
    }

    // DCT weights (independent, before sync): kk = tid>>3, gg = tid&7
    const int kk = tid >> 3;
    const int gg = tid & 7;
    float wdct[4];
#pragma unroll
    for (int u = 0; u < 4; u++) {
        int j = gg * 4 + u;
        wdct[u] = cospif((float)(kk * (2 * j + 1)) * (1.0f / 64.0f));
    }
    __syncthreads();

    // ---- prologue phase 2: DCT partials + in-warp 8-lane reduce -----------
    {
        float part = 0.0f;
#pragma unroll
        for (int u = 0; u < 4; u++)
            part = fmaf(s_f[gg * 4 + u], wdct[u], part);
        // partials for coefficient kk live in 8 consecutive lanes; reduce
#pragma unroll
        for (int off = 4; off; off >>= 1)
            part += __shfl_xor_sync(0xFFFFFFFFu, part, off);
        float e = part * (1.0f / 16.0f);
        if (kk == 0) e *= 0.5f;              // e_0 = c_0/2
        if (gg == 0 && kk < NCOEF) s_e[kk] = e;
    }
    __syncthreads();

    // ---- prologue phase 3: every thread -> monomial coeffs (no sync) ------
    float cs[NCOEF];
#pragma unroll
    for (int j = 0; j < NCOEF; j++) {
        float acc = 0.0f;
#pragma unroll
        for (int k = 0; k < NCOEF; k++)
            acc = fmaf(s_e[k], c_T[k][j], acc);
        cs[j] = acc;
    }

    const float w0 = conv_w[0], w1 = conv_w[1];
    const float w2 = conv_w[2], w3 = conv_w[3];
    const float bb = conv_b[0];

    // ---- pipelined main loop (pointer-increment addressing) ---------------
    while (valid) {
        float l0 = fmaf(v0.x, w0, fmaf(v0.y, w1, fmaf(v0.z, w2, fmaf(v0.w, w3, bb))));
        float l1 = fmaf(v1.x, w0, fmaf(v1.y, w1, fmaf(v1.z, w2, fmaf(v1.w, w3, bb))));
        float l2 = fmaf(v2.x, w0, fmaf(v2.y, w1, fmaf(v2.z, w2, fmaf(v2.w, w3, bb))));
        float l3 = fmaf(v3.x, w0, fmaf(v3.y, w1, fmaf(v3.z, w2, fmaf(v3.w, w3, bb))));
        float t0 = fast_tanh(0.5f * l0);
        float t1 = fast_tanh(0.5f * l1);
        float t2 = fast_tanh(0.5f * l2);
        float t3 = fast_tanh(0.5f * l3);

        // issue NEXT chunk's loads before the Horner chain + stores
        chunk += nWarps;
        valid = chunk < nChunks;
        p += step;
        if (valid) {
            v0 = __ldcs(p);
            v1 = __ldcs(p + 32);
            v2 = __ldcs(p + 64);
            v3 = __ldcs(p + 96);
        }

        unsigned long long tA, tB;
        PACK2(tA, t0, t1);
        PACK2(tB, t2, t3);

        unsigned long long ck2;
        PACK2(ck2, cs[NCOEF - 1], cs[NCOEF - 1]);
        unsigned long long hA = ck2, hB = ck2;
#pragma unroll
        for (int k = NCOEF - 2; k >= 0; k--) {
            PACK2(ck2, cs[k], cs[k]);
            FMA2(hA, tA, hA, ck2);
            FMA2(hB, tB, hB, ck2);
        }

        float r0, r1, r2, r3;
        UNPACK2(r0, r1, hA);
        UNPACK2(r2, r3, hB);
        __stcs(o,      r0);
        __stcs(o + 32, r1);
        __stcs(o + 64, r2);
        __stcs(o + 96, r3);
        o += step;
    }

    // defensive tail for n % 128 != 0 (empty for N = 2^23)
    for (int k = (nChunks << 7) + gid; k < n; k += gridDim.x * blockDim.x) {
        float4 v = data[k];
        float l = fmaf(v.x, w0, fmaf(v.y, w1, fmaf(v.z, w2, fmaf(v.w, w3, bb))));
        float t = fast_tanh(0.5f * l);
        float h = cs[NCOEF - 1];
#pragma unroll
        for (int q = NCOEF - 2; q >= 0; q--)
            h = fmaf(t, h, cs[q]);
        out[k] = h;
    }
}

extern "C" void kernel_launch(void* const* d_in, const int* in_sizes, int n_in,
                              void* d_out, int out_size) {
    const float* data   = (const float*)d_in[0];   // [N, 2, 2]
    const float* conv_w = (const float*)d_in[1];   // [2, 2]
    const float* conv_b = (const float*)d_in[2];   // [1]
    const float* basis  = (const float*)d_in[3];   // [8, 4]
    const float* w1     = (const float*)d_in[4];   // [8, 16]
    const float* b1     = (const float*)d_in[5];   // [16]
    const float* w2     = (const float*)d_in[6];   // [16, 1]
    const float* b2     = (const float*)d_in[7];   // [1]

    const int n       = in_sizes[0] / 4;   // patches
    const int nChunks = n >> 7;            // 128-patch warp chunks

    // single launch: 1064 blocks = exactly 7 CTAs/SM x 152 SMs
    hybridconv_kernel<<<1064, 256>>>(
        (const float4*)data, conv_w, conv_b, basis, w1, b1, w2, b2,
        (float*)d_out, nChunks, n);
}